// round 16
// baseline (speedup 1.0000x reference)
#include <cuda_runtime.h>
#include <cuda_fp16.h>

// Edge_27547920236817: B=16, C=3, H=W=512 f32 in; out (B, C*8, H, W) f32.
// R15: 1 px/thread (proven occ-88% structure) + WITHIN-PIXEL f16x2 packing:
//  - 22 e-sum tanh terms -> 11 tanh.approx.f16x2 (doubled-weight terms occupy
//    both halves, so lo+hi applies the weight for free)
//  - pair accumulation in f16x2 (HADD2), ONE ALU bit-trick unpack per group,
//    final lo+hi add in f32 (no f16 rounding at magnitude ~6, no XU F2F)
//  - s01/sn11 packed into one tanh.approx.f16x2
//  - s10/s11 free via copysign of th(|d|) from the ad-chain
// XU instrs per pixel: 31 -> 19.

#define HH 512
#define WW 512

__device__ __forceinline__ float th(float x) {
    float y;
    asm("tanh.approx.f32 %0, %1;" : "=f"(y) : "f"(x));
    return y;
}

// pack two f32 -> f16x2 (F2FP, ALU pipe), one tanh.approx.f16x2 (XU)
__device__ __forceinline__ __half2 th2p(float a, float b) {
    __half2 h = __floats2half2_rn(a, b);
    unsigned u = *reinterpret_cast<unsigned*>(&h);
    unsigned v;
    asm("tanh.approx.f16x2 %0, %1;" : "=r"(v) : "r"(u));
    return *reinterpret_cast<__half2*>(&v);
}

// f16x2 -> two f32 via integer ops only (no F2F on the XU pipe).
// Exact for normal halves; |err|<=2^-14 near zero (harmless here).
__device__ __forceinline__ float2 h2f2(__half2 h) {
    unsigned u = *reinterpret_cast<unsigned*>(&h);
    unsigned lo = ((u & 0x8000u) << 16) | (((u & 0x7fffu) << 13) + 0x38000000u);
    unsigned hi = (u & 0x80000000u)     | (((u >> 3) & 0x0FFFE000u) + 0x38000000u);
    return make_float2(__uint_as_float(lo), __uint_as_float(hi));
}

// lo+hi of a packed pair-sum, in f32
__device__ __forceinline__ float sumhalves(__half2 q) {
    float2 f = h2f2(q);
    return f.x + f.y;
}

__global__ void __launch_bounds__(256) edge_kernel(const float* __restrict__ in,
                                                   float* __restrict__ out) {
    int i  = blockIdx.x * blockDim.x + threadIdx.x;   // index within plane
    int x  = i & (WW - 1);
    int y  = i >> 9;
    int bc = blockIdx.y;          // b*3 + c
    int b  = bc / 3;
    int c  = bc - 3 * b;

    float* o = out + (((b * 24 + c * 8) << 18) + i);

    if (x < 2 || x >= WW - 2 || y < 2 || y >= HH - 2) {
        #pragma unroll
        for (int k = 0; k < 8; k++) o[k << 18] = 0.0f;
        return;
    }

    int cm = (c + 2) % 3;   // rl a=+1 -> channel (c-1)%3
    int cp = (c + 1) % 3;   // rl a=-1 -> channel (c+1)%3

    const float* p  = in + (bc << 18);
    const float* pa = in + ((b * 3 + cm) << 18);
    const float* pc = in + ((b * 3 + cp) << 18);

    int r   = i;
    int rm1 = r - WW, rp1 = r + WW, rm2 = r - 2 * WW;

    const float S = 5.0f;   // sigmoid(10t) = 0.5 + 0.5*tanh(5t)

    // own-channel neighborhood (scaled by 5)
    float v00   = S * __ldg(p + r);
    float vm1m1 = S * __ldg(p + rm1 - 1);
    float vm10  = S * __ldg(p + rm1);
    float vm1p1 = S * __ldg(p + rm1 + 1);
    float v0m1  = S * __ldg(p + r - 1);
    float v0p1  = S * __ldg(p + r + 1);
    float vp1m1 = S * __ldg(p + rp1 - 1);
    float vp10  = S * __ldg(p + rp1);
    float vp1p1 = S * __ldg(p + rp1 + 1);
    float vm20  = S * __ldg(p + rm2);

    // channel cm
    float a00   = S * __ldg(pa + r);
    float a0m1  = S * __ldg(pa + r - 1);
    float a0p1  = S * __ldg(pa + r + 1);
    float am10  = S * __ldg(pa + rm1);
    float am2p1 = S * __ldg(pa + rm2 + 1);
    float am2m1 = S * __ldg(pa + rm2 - 1);

    // channel cp
    float cm10  = S * __ldg(pc + rm1);
    float cm2m1 = S * __ldg(pc + rm2 - 1);
    float c0m1  = S * __ldg(pc + r - 1);

    // scaled diffs
    float d10   = vm10  - v00;
    float dn10  = vp10  - v00;
    float d01   = v0m1  - v00;
    float dn01  = v0p1  - v00;
    float d11   = vm1m1 - v00;
    float dnn11 = vp1p1 - v00;
    float dn11  = vp1m1 - v00;
    float d1n1  = vm1p1 - v00;

    float rd01a  = a0m1 - a00;      // rl(.,(1,0))
    float rdn01a = a0p1 - a00;
    float rd10u  = vm20  - vm10;    // rl(.,(0,1))
    float rdn10u = v00   - vm10;
    float rd01u  = vm1m1 - vm10;
    float rdn11b = a0m1  - am10;    // rl(.,(1,1))
    float rd1n1b = am2p1 - am10;
    float rd11b  = am2m1 - am10;
    float rd11c  = cm2m1 - cm10;    // rl(.,(-1,1))
    float rdn11c = c0m1  - cm10;

    // ---- ad-chain (3 f32 XU) ----
    float ad10r = fabsf(d10);
    float t10a  = th(ad10r);                               // XU
    float ad10  = ad10r * fmaf(0.5f, t10a, 0.5f);
    float s10   = fmaf(0.5f, copysignf(t10a, d10), 0.5f);  // free
    float ad01  = fabsf(d01) * fmaf(0.5f, th(ad10), 0.5f); // XU
    float ad11r = fabsf(d11);
    float t11a  = th(ad11r);                               // XU
    float ad11  = ad11r * fmaf(0.5f, t11a, 0.5f);
    float s11   = fmaf(0.5f, copysignf(t11a, d11), 0.5f);  // free
    float adn11 = fabsf(dn11);

    // ---- e-sums: 11 tanh.approx.f16x2, pairs summed in f16x2, finished in f32 ----
    // group 10: terms (1,1,1,1) + rd01a weighted 2 packed in both halves
    float T10;
    {
        __half2 P1 = th2p(ad10 - fabsf(d01),   ad10 - fabsf(dn01));
        __half2 P2 = th2p(ad10 - fabsf(dn10),  ad10 - fabsf(rdn01a));
        __half2 P3 = th2p(ad10 - fabsf(rd01a), ad10 - fabsf(rd01a));  // w=2 via lo+hi
        T10 = sumhalves(__hadd2(__hadd2(P1, P2), P3));
    }
    // group 01: 6 terms
    float T01;
    {
        __half2 P1 = th2p(ad01 - fabsf(d10),   ad01 - fabsf(dn10));
        __half2 P2 = th2p(ad01 - fabsf(dn01),  ad01 - fabsf(rd10u));
        __half2 P3 = th2p(ad01 - fabsf(rdn10u),ad01 - fabsf(rd01u));
        T01 = sumhalves(__hadd2(__hadd2(P1, P2), P3));
    }
    // group 11: 6 terms
    float T11;
    {
        __half2 P1 = th2p(ad11 - fabsf(dn11),  ad11 - fabsf(d1n1));
        __half2 P2 = th2p(ad11 - fabsf(dnn11), ad11 - fabsf(rdn11b));
        __half2 P3 = th2p(ad11 - fabsf(rd1n1b),ad11 - fabsf(rd11b));
        T11 = sumhalves(__hadd2(__hadd2(P1, P2), P3));
    }
    // group n11: (1,1,1,1) + rdn11c weighted 2 packed in both halves
    float Tn11;
    {
        __half2 P1 = th2p(adn11 - fabsf(d11),   adn11 - fabsf(d1n1));
        __half2 P2 = th2p(adn11 - fabsf(dnn11), adn11 - fabsf(rd11c));
        __half2 P3 = th2p(adn11 - fabsf(rdn11c),adn11 - fabsf(rdn11c)); // w=2
        Tn11 = sumhalves(__hadd2(__hadd2(P1, P2), P3));
    }

    // ---- packed sign sigmoids for s01, sn11 (1 XU) ----
    float s01, sn11;
    {
        float2 sp = h2f2(th2p(d01, dn11));
        s01  = fmaf(0.5f, sp.x, 0.5f);
        sn11 = fmaf(0.5f, sp.y, 0.5f);
    }

    // ---- gates (4 f32 XU) + outputs ----
    float g10  = fmaf(0.5f, th(fmaf(2.5f, T10,  -5.0f)), 0.5f);
    float g01  = fmaf(0.5f, th(fmaf(2.5f, T01,  -5.0f)), 0.5f);
    float g11  = fmaf(0.5f, th(fmaf(2.5f, T11,  -5.0f)), 0.5f);
    float gn11 = fmaf(0.5f, th(fmaf(2.5f, Tn11, -5.0f)), 0.5f);

    float o0 = g10 * s10;
    float o2 = g01 * s01;
    float o4 = g11 * s11;
    float o6 = gn11 * sn11;

    o[0 << 18] = o0;
    o[1 << 18] = g10 - o0;
    o[2 << 18] = o2;
    o[3 << 18] = o2;          // reference quirk: e01n == e01
    o[4 << 18] = o4;
    o[5 << 18] = g11 - o4;
    o[6 << 18] = o6;
    o[7 << 18] = gn11 - o6;
}

extern "C" void kernel_launch(void* const* d_in, const int* in_sizes, int n_in,
                              void* d_out, int out_size) {
    const float* x = (const float*)d_in[0];
    float* out = (float*)d_out;
    dim3 grid((HH * WW) / 256, 16 * 3);
    edge_kernel<<<grid, 256>>>(x, out);
}

// round 17
// speedup vs baseline: 1.0993x; 1.0993x over previous
#include <cuda_runtime.h>
#include <cuda_fp16.h>

// Edge_27547920236817: B=16, C=3, H=W=512 f32 in; out (B, C*8, H, W) f32.
// R16 = R14 (proven 94.9us, 31 f32-tanh/px, occ 89%) with ONE change axis:
//  - the 4 gate tanhs -> 2 tanh.approx.f16x2, the 2 sign tanhs -> 1 f16x2.
//    Args stay f32 until one F2FP pack; results unpacked by an ALU bit trick
//    (no XU F2F). Overhead ~21 ALU instrs, no deep chains.
//  - 3D grid: blockIdx.y = c, blockIdx.z = b (no div/mod per thread).
// Decisive probe: if tanh.approx.f16x2 is full-rate, XU 31->28 slots (~ -6%);
// if half-rate, neutral and f16 is closed for good.

#define HH 512
#define WW 512

__device__ __forceinline__ float th(float x) {
    float y;
    asm("tanh.approx.f32 %0, %1;" : "=f"(y) : "f"(x));
    return y;
}

// pack two f32 -> f16x2 (F2FP), one tanh.approx.f16x2
__device__ __forceinline__ __half2 th2p(float a, float b) {
    __half2 h = __floats2half2_rn(a, b);
    unsigned u = *reinterpret_cast<unsigned*>(&h);
    unsigned v;
    asm("tanh.approx.f16x2 %0, %1;" : "=r"(v) : "r"(u));
    return *reinterpret_cast<__half2*>(&v);
}

// f16x2 -> two f32 via integer ops only (exact for normal halves)
__device__ __forceinline__ float2 h2f2(__half2 h) {
    unsigned u = *reinterpret_cast<unsigned*>(&h);
    unsigned lo = ((u & 0x8000u) << 16) | (((u & 0x7fffu) << 13) + 0x38000000u);
    unsigned hi = (u & 0x80000000u)     | (((u >> 3) & 0x0FFFE000u) + 0x38000000u);
    return make_float2(__uint_as_float(lo), __uint_as_float(hi));
}

__global__ void __launch_bounds__(256) edge_kernel(const float* __restrict__ in,
                                                   float* __restrict__ out) {
    int i  = blockIdx.x * blockDim.x + threadIdx.x;   // index within plane
    int x  = i & (WW - 1);
    int y  = i >> 9;
    int c  = blockIdx.y;          // 0..2
    int b  = blockIdx.z;          // 0..15
    int bc = b * 3 + c;

    float* o = out + (((b * 24 + c * 8) << 18) + i);

    if (x < 2 || x >= WW - 2 || y < 2 || y >= HH - 2) {
        #pragma unroll
        for (int k = 0; k < 8; k++) o[k << 18] = 0.0f;
        return;
    }

    int cm = (c + 2) % 3;   // rl a=+1 -> channel (c-1)%3
    int cp = (c + 1) % 3;   // rl a=-1 -> channel (c+1)%3

    const float* p  = in + (bc << 18);
    const float* pa = in + ((b * 3 + cm) << 18);
    const float* pc = in + ((b * 3 + cp) << 18);

    int r   = i;
    int rm1 = r - WW, rp1 = r + WW, rm2 = r - 2 * WW;

    const float S = 5.0f;   // sigmoid(10t) = 0.5 + 0.5*tanh(5t)

    // own-channel neighborhood (scaled by 5)
    float v00   = S * __ldg(p + r);
    float vm1m1 = S * __ldg(p + rm1 - 1);
    float vm10  = S * __ldg(p + rm1);
    float vm1p1 = S * __ldg(p + rm1 + 1);
    float v0m1  = S * __ldg(p + r - 1);
    float v0p1  = S * __ldg(p + r + 1);
    float vp1m1 = S * __ldg(p + rp1 - 1);
    float vp10  = S * __ldg(p + rp1);
    float vp1p1 = S * __ldg(p + rp1 + 1);
    float vm20  = S * __ldg(p + rm2);

    // channel cm
    float a00   = S * __ldg(pa + r);
    float a0m1  = S * __ldg(pa + r - 1);
    float a0p1  = S * __ldg(pa + r + 1);
    float am10  = S * __ldg(pa + rm1);
    float am2p1 = S * __ldg(pa + rm2 + 1);
    float am2m1 = S * __ldg(pa + rm2 - 1);

    // channel cp
    float cm10  = S * __ldg(pc + rm1);
    float cm2m1 = S * __ldg(pc + rm2 - 1);
    float c0m1  = S * __ldg(pc + r - 1);

    // scaled diffs
    float d10   = vm10  - v00;
    float dn10  = vp10  - v00;
    float d01   = v0m1  - v00;
    float dn01  = v0p1  - v00;
    float d11   = vm1m1 - v00;
    float dnn11 = vp1p1 - v00;
    float dn11  = vp1m1 - v00;
    float d1n1  = vm1p1 - v00;

    float rd01a  = a0m1 - a00;      // rl(.,(1,0))
    float rdn01a = a0p1 - a00;
    float rd10u  = vm20  - vm10;    // rl(.,(0,1))
    float rdn10u = v00   - vm10;
    float rd01u  = vm1m1 - vm10;
    float rdn11b = a0m1  - am10;    // rl(.,(1,1))
    float rd1n1b = am2p1 - am10;
    float rd11b  = am2m1 - am10;
    float rd11c  = cm2m1 - cm10;    // rl(.,(-1,1))
    float rdn11c = c0m1  - cm10;

    // ---- ad-chain (3 f32 XU) ----
    float ad10r = fabsf(d10);
    float t10a  = th(ad10r);
    float ad10  = ad10r * fmaf(0.5f, t10a, 0.5f);
    float s10   = fmaf(0.5f, copysignf(t10a, d10), 0.5f);   // free sign sigmoid
    float ad01  = fabsf(d01) * fmaf(0.5f, th(ad10), 0.5f);
    float ad11r = fabsf(d11);
    float t11a  = th(ad11r);
    float ad11  = ad11r * fmaf(0.5f, t11a, 0.5f);
    float s11   = fmaf(0.5f, copysignf(t11a, d11), 0.5f);   // free sign sigmoid
    float adn11 = fabsf(dn11);

    // ---- e-sums: 22 f32 XU (unchanged from R14) ----
    float T10 = th(ad10 - fabsf(d01)) + th(ad10 - fabsf(dn01)) + th(ad10 - fabsf(dn10))
              + 2.0f * th(ad10 - fabsf(rd01a)) + th(ad10 - fabsf(rdn01a));
    float T01 = th(ad01 - fabsf(d10)) + th(ad01 - fabsf(dn10)) + th(ad01 - fabsf(dn01))
              + th(ad01 - fabsf(rd10u)) + th(ad01 - fabsf(rdn10u)) + th(ad01 - fabsf(rd01u));
    float T11 = th(ad11 - fabsf(dn11)) + th(ad11 - fabsf(d1n1)) + th(ad11 - fabsf(dnn11))
              + th(ad11 - fabsf(rdn11b)) + th(ad11 - fabsf(rd1n1b)) + th(ad11 - fabsf(rd11b));
    float Tn11 = th(adn11 - fabsf(d11)) + th(adn11 - fabsf(d1n1)) + th(adn11 - fabsf(dnn11))
               + th(adn11 - fabsf(rd11c)) + 2.0f * th(adn11 - fabsf(rdn11c));

    // ---- gates: 4 tanh -> 2 f16x2 XU; signs: 2 tanh -> 1 f16x2 XU ----
    float ga10 = fmaf(2.5f, T10,  -5.0f);
    float ga01 = fmaf(2.5f, T01,  -5.0f);
    float ga11 = fmaf(2.5f, T11,  -5.0f);
    float gan  = fmaf(2.5f, Tn11, -5.0f);

    float2 gA = h2f2(th2p(ga10, ga01));
    float2 gB = h2f2(th2p(ga11, gan));
    float2 sp = h2f2(th2p(d01, dn11));

    float g10  = fmaf(0.5f, gA.x, 0.5f);
    float g01  = fmaf(0.5f, gA.y, 0.5f);
    float g11  = fmaf(0.5f, gB.x, 0.5f);
    float gn11 = fmaf(0.5f, gB.y, 0.5f);
    float s01  = fmaf(0.5f, sp.x, 0.5f);
    float sn11 = fmaf(0.5f, sp.y, 0.5f);

    float o0 = g10 * s10;
    float o2 = g01 * s01;
    float o4 = g11 * s11;
    float o6 = gn11 * sn11;

    o[0 << 18] = o0;
    o[1 << 18] = g10 - o0;
    o[2 << 18] = o2;
    o[3 << 18] = o2;          // reference quirk: e01n == e01
    o[4 << 18] = o4;
    o[5 << 18] = g11 - o4;
    o[6 << 18] = o6;
    o[7 << 18] = gn11 - o6;
}

extern "C" void kernel_launch(void* const* d_in, const int* in_sizes, int n_in,
                              void* d_out, int out_size) {
    const float* x = (const float*)d_in[0];
    float* out = (float*)d_out;
    dim3 grid((HH * WW) / 256, 3, 16);
    edge_kernel<<<grid, 256>>>(x, out);
}